// round 14
// baseline (speedup 1.0000x reference)
#include <cuda_runtime.h>
#include <cuda_fp16.h>
#include <cstdint>
#include <cstddef>

// ---------------- problem constants ----------------
#define DD     1024
#define PCOLS  405       // 1 + 80 + 324
#define NTILE  4
#define BNL    104       // live cols per tile
#define BNP    112       // padded rows per tile
#define NF     300
#define NMAX   65536
#define BM     128
#define BK     64        // fp16: 64 halves = 128B rows -> SW128 swizzle
#define NCHUNK (DD / BK) // 16
#define NSTAGE 3

#define A_BYTES  (BM * 128)              // 16384
#define B_BYTES  (BNP * 128)             // 14336
#define STAGE_SZ (A_BYTES + B_BYTES)     // 30720
#define SMEM_DYN (NSTAGE * STAGE_SZ)     // 92160 -> 2 CTAs/SM
#define LDC      120

// ---------------- device scratch ----------------
__device__ __half g_xh[(size_t)NMAX * DD];        // 128 MB fp16 x
__device__ __half g_Wh[(size_t)NTILE * BNP * DD];
__device__ float  g_bias[NTILE * BNP];

// ---------------- helpers ----------------
__device__ __forceinline__ uint32_t smem_u32(const void* p) {
    uint32_t a;
    asm("{ .reg .u64 t; cvta.to.shared.u64 t, %1; cvt.u32.u64 %0, t; }" : "=r"(a) : "l"(p));
    return a;
}
__device__ __forceinline__ void cpa16(uint32_t dst, const void* src) {
    asm volatile("cp.async.cg.shared.global [%0], [%1], 16;" :: "r"(dst), "l"(src));
}
__device__ __forceinline__ void ldsm4(uint32_t r[4], uint32_t addr) {
    asm volatile("ldmatrix.sync.aligned.m8n8.x4.shared.b16 {%0,%1,%2,%3}, [%4];"
        : "=r"(r[0]), "=r"(r[1]), "=r"(r[2]), "=r"(r[3]) : "r"(addr));
}
__device__ __forceinline__ void mma16(float d[4], const uint32_t a[4], uint32_t b0, uint32_t b1) {
    asm volatile(
        "mma.sync.aligned.m16n8k16.row.col.f32.f16.f16.f32 "
        "{%0,%1,%2,%3}, {%4,%5,%6,%7}, {%8,%9}, {%0,%1,%2,%3};"
        : "+f"(d[0]), "+f"(d[1]), "+f"(d[2]), "+f"(d[3])
        : "r"(a[0]), "r"(a[1]), "r"(a[2]), "r"(a[3]), "r"(b0), "r"(b1));
}
__device__ __forceinline__ uint4 pack8(float4 a, float4 b) {
    __half2 h0 = __floats2half2_rn(a.x, a.y);
    __half2 h1 = __floats2half2_rn(a.z, a.w);
    __half2 h2 = __floats2half2_rn(b.x, b.y);
    __half2 h3 = __floats2half2_rn(b.z, b.w);
    uint4 u;
    u.x = *reinterpret_cast<uint32_t*>(&h0);
    u.y = *reinterpret_cast<uint32_t*>(&h1);
    u.z = *reinterpret_cast<uint32_t*>(&h2);
    u.w = *reinterpret_cast<uint32_t*>(&h3);
    return u;
}

// ---------------- k_cvt: x fp32 -> fp16, streaming (R12-proven) ----------------
__global__ void k_cvt(const float4* __restrict__ xi, int n8) {
    uint4* xo = reinterpret_cast<uint4*>(g_xh);
    int i = blockIdx.x * blockDim.x + threadIdx.x;
    if (i < n8) {
        float4 a = xi[2 * i], b = xi[2 * i + 1];
        xo[i] = pack8(a, b);
    }
}

// ---------------- k_foldcopy: sem fold [0,80) + cls/bbox copy [80,528) ----------
__global__ void k_foldcopy(const float* __restrict__ Wcls, const float* __restrict__ bcls,
                           const float* __restrict__ Wsem, const float* __restrict__ bsem,
                           const float* __restrict__ Wbb,  const float* __restrict__ bbb,
                           const float* __restrict__ semm) {
    __shared__ float ssm[4 * NF];
    __shared__ float sscale[4];
    const int blk = blockIdx.x, t = threadIdx.x;

    if (blk < 80) {
        // ---- fold: 4 rows x 256 cols per block ----
        const int cg = blk & 3, rg = blk >> 2;
        const int wid = t >> 5, lane = t & 31;
        const int r0 = rg * 4, c0 = cg * 256;
        if (wid < 4) {
            const float* src = semm + (size_t)(r0 + wid) * NF;
            float ss = 0.f;
            for (int f = lane; f < NF; f += 32) { float v = src[f]; ss += v * v; }
            for (int o = 16; o; o >>= 1) ss += __shfl_xor_sync(~0u, ss, o);
            if (lane == 0) sscale[wid] = 8.0f * rsqrtf(ss);
        }
        __syncthreads();
        for (int idx = t; idx < 4 * NF; idx += 256) {
            int ri = idx / NF, f = idx - ri * NF;
            ssm[ri * NF + f] = semm[(size_t)(r0 + ri) * NF + f] * sscale[ri];
        }
        __syncthreads();
        float acc[4] = {0.f, 0.f, 0.f, 0.f};
        const float* wp = Wsem + c0 + t;
#pragma unroll 10
        for (int f = 0; f < NF; f++) {
            float w = wp[(size_t)f * DD];
#pragma unroll
            for (int ri = 0; ri < 4; ri++) acc[ri] += ssm[ri * NF + f] * w;
        }
#pragma unroll
        for (int ri = 0; ri < 4; ri++)
            g_Wh[(size_t)(1 + r0 + ri) * DD + c0 + t] = __float2half_rn(acc[ri]);
        if (cg == 0 && wid < 4) {
            float bb = 0.f;
            for (int f = lane; f < NF; f += 32) bb += ssm[wid * NF + f] * bsem[f];
            for (int o = 16; o; o >>= 1) bb += __shfl_xor_sync(~0u, bb, o);
            if (lane == 0) g_bias[1 + r0 + wid] = bb;
        }
        return;
    }
    // ---- copy ----
    const int p = blk - 80;
    const int tile = p / BNP, r = p - tile * BNP;
    const int j = tile * BNL + r;
    __half* wo = g_Wh + (size_t)p * DD;
    if (r >= BNL || j >= PCOLS) {
        for (int d = t; d < DD; d += 256) wo[d] = __float2half_rn(0.f);
        if (t == 0) g_bias[p] = 0.f;
    } else if (j == 0) {
        for (int d = t; d < DD; d += 256) wo[d] = __float2half_rn(Wcls[d]);
        if (t == 0) g_bias[p] = bcls[0];
    } else if (j <= 80) {
        // written by fold blocks
    } else {
        const int i = j - 81;
        for (int d = t; d < DD; d += 256) wo[d] = __float2half_rn(Wbb[(size_t)i * DD + d]);
        if (t == 0) g_bias[p] = bbb[i];
    }
}

// ---------------- main GEMM: fp16 m16n8k16, spread cp.async issue ----------------
__device__ __forceinline__ void issueA(uint32_t sbase, const __half* __restrict__ xs, int tid) {
#pragma unroll
    for (int i = 0; i < 4; i++) {               // A: 128 rows x 8 quads = 1024
        int seg = tid + i * 256;
        int row = seg >> 3, q = seg & 7;
        cpa16(sbase + (uint32_t)(row * 128 + ((q ^ (row & 7)) << 4)),
              xs + (size_t)row * DD + q * 8);
    }
}
__device__ __forceinline__ void issueB(uint32_t sbase, const __half* __restrict__ ws, int tid) {
#pragma unroll
    for (int i = 0; i < 4; i++) {               // B: 112 rows x 8 quads = 896
        int seg = tid + i * 256;
        if (seg < BNP * 8) {
            int row = seg >> 3, q = seg & 7;
            cpa16(sbase + (uint32_t)(A_BYTES + row * 128 + ((q ^ (row & 7)) << 4)),
                  ws + (size_t)row * DD + q * 8);
        }
    }
    asm volatile("cp.async.commit_group;" ::: "memory");
}

template <int NJ0, int NJ1, int NB1, int LIVE>
__device__ __forceinline__ void gemm_body(char* sm, float* __restrict__ out, int N, int nt) {
    const int tid = threadIdx.x, wid = tid >> 5, lane = tid & 31;
    const int warp_m = wid & 3;
    const int warp_n = wid >> 2;
    const size_t row0 = (size_t)blockIdx.y * BM;
    const size_t NS = (size_t)N * 81;
    const int NJ = warp_n ? NJ1 : NJ0;
    const int colbase = warp_n ? NB1 : 0;

    uint32_t st[NSTAGE];
#pragma unroll
    for (int s = 0; s < NSTAGE; s++) st[s] = smem_u32(sm + s * STAGE_SZ);

    const __half* xrow0 = g_xh + row0 * DD;
    const __half* wrow0 = g_Wh + (size_t)nt * BNP * DD;

    const int rAr = warp_m * 32 + ((lane >> 3) & 1) * 8 + (lane & 7);
    const int qbA = lane >> 4;
    const uint32_t abase0 = (uint32_t)rAr * 128, abase1 = (uint32_t)(rAr + 16) * 128;
    const uint32_t axor = (uint32_t)(rAr & 7);
    const int rBr = colbase + (lane >> 4) * 8 + (lane & 7);
    const int qbB = (lane >> 3) & 1;
    uint32_t bbase[4];
#pragma unroll
    for (int g = 0; g < 4; g++) bbase[g] = (uint32_t)(rBr + g * 16) * 128;
    const uint32_t bxor = (uint32_t)(rBr & 7);

    float acc[2][NJ0][4];
#pragma unroll
    for (int mi = 0; mi < 2; mi++)
#pragma unroll
        for (int nj = 0; nj < NJ0; nj++)
#pragma unroll
            for (int e = 0; e < 4; e++) acc[mi][nj][e] = 0.f;

    issueA(st[0], xrow0, tid);           issueB(st[0], wrow0, tid);
    issueA(st[1], xrow0 + BK, tid);      issueB(st[1], wrow0 + BK, tid);

    for (int c = 0; c < NCHUNK; c++) {
        uint32_t Ab = st[c % NSTAGE], Bb = Ab + A_BYTES;
        if (c == NCHUNK - 1) asm volatile("cp.async.wait_group 0;" ::: "memory");
        else                 asm volatile("cp.async.wait_group 1;" ::: "memory");
        __syncthreads();
        const bool pre = (c + 2 < NCHUNK);
        const uint32_t stn = st[(c + 2) % NSTAGE];

#pragma unroll
        for (int kq = 0; kq < 4; kq++) {
            uint32_t a0[4], a1[4];
            uint32_t qsel = (uint32_t)((2 * kq + qbA) ^ axor) << 4;
            ldsm4(a0, Ab + abase0 + qsel);
            ldsm4(a1, Ab + abase1 + qsel);
            uint32_t qselB = (uint32_t)((2 * kq + qbB) ^ bxor) << 4;
            if (warp_n == 0) {
#pragma unroll
                for (int g = 0; g < 4; g++) {
                    if (g < (NJ0 + 1) / 2) {
                        uint32_t b[4];
                        ldsm4(b, Bb + bbase[g] + qselB);
                        if (2 * g < NJ0)     { mma16(acc[0][2 * g],     a0, b[0], b[1]);
                                               mma16(acc[1][2 * g],     a1, b[0], b[1]); }
                        if (2 * g + 1 < NJ0) { mma16(acc[0][2 * g + 1], a0, b[2], b[3]);
                                               mma16(acc[1][2 * g + 1], a1, b[2], b[3]); }
                    }
                }
            } else {
#pragma unroll
                for (int g = 0; g < 4; g++) {
                    if (g < (NJ1 + 1) / 2) {
                        uint32_t b[4];
                        ldsm4(b, Bb + bbase[g] + qselB);
                        if (2 * g < NJ1)     { mma16(acc[0][2 * g],     a0, b[0], b[1]);
                                               mma16(acc[1][2 * g],     a1, b[0], b[1]); }
                        if (2 * g + 1 < NJ1) { mma16(acc[0][2 * g + 1], a0, b[2], b[3]);
                                               mma16(acc[1][2 * g + 1], a1, b[2], b[3]); }
                    }
                }
            }
            // spread the refill: A-half after kq0, B-half (+commit) after kq1
            if (kq == 0 && pre) issueA(stn, xrow0 + (size_t)(c + 2) * BK, tid);
            if (kq == 1 && pre) issueB(stn, wrow0 + (size_t)(c + 2) * BK, tid);
        }
    }
    __syncthreads();

    // ---- epilogue ----
    float* sC = (float*)sm;
    const int tr = lane >> 2, tc2 = (lane & 3) * 2;
#pragma unroll
    for (int mi = 0; mi < 2; mi++)
#pragma unroll
        for (int nj = 0; nj < NJ0; nj++)
            if (nj < NJ) {
                int r = warp_m * 32 + mi * 16 + tr;
                int cc = colbase + nj * 8 + tc2;
                *(float2*)&sC[r * LDC + cc]       = make_float2(acc[mi][nj][0], acc[mi][nj][1]);
                *(float2*)&sC[(r + 8) * LDC + cc] = make_float2(acc[mi][nj][2], acc[mi][nj][3]);
            }
    __syncthreads();

    float* outb = out + NS;
    const int jbase = nt * BNL;
    const float* biasp = g_bias + nt * BNP;
    for (int e = tid; e < BM * LIVE; e += 256) {
        int row = e / LIVE, n = e - row * LIVE;
        int j = jbase + n;
        float v = sC[row * LDC + n] + __ldg(biasp + n);
        size_t gr = row0 + row;
        if (j < 81) __stcs(&out[gr * 81 + j], v);
        else        __stcs(&outb[gr * 324 + (j - 81)], v);
    }
}

__global__ __launch_bounds__(256, 2) void k_main(float* __restrict__ out, int N) {
    extern __shared__ char sm[];
    const int nt = blockIdx.x;
    if (nt < 3) gemm_body<7, 6, 56, 104>(sm, out, N, nt);
    else        gemm_body<6, 6, 48, 93>(sm, out, N, nt);
}

// ---------------- launch ----------------
extern "C" void kernel_launch(void* const* d_in, const int* in_sizes, int n_in,
                              void* d_out, int out_size) {
    const float* x    = (const float*)d_in[0];
    const float* Wcls = (const float*)d_in[1];
    const float* bcls = (const float*)d_in[2];
    const float* Wsem = (const float*)d_in[3];
    const float* bsem = (const float*)d_in[4];
    const float* Wbb  = (const float*)d_in[5];
    const float* bbb  = (const float*)d_in[6];
    const float* semm = (const float*)d_in[7];
    float* out = (float*)d_out;
    int N = in_sizes[0] / DD;

    cudaFuncSetAttribute(k_main, cudaFuncAttributeMaxDynamicSharedMemorySize, SMEM_DYN);

    int n8 = N * DD / 8;
    k_cvt<<<(n8 + 255) / 256, 256>>>((const float4*)x, n8);
    k_foldcopy<<<80 + NTILE * BNP, 256>>>(Wcls, bcls, Wsem, bsem, Wbb, bbb, semm);
    dim3 grid(NTILE, N / BM);
    k_main<<<grid, 256, SMEM_DYN>>>(out, N);
}

// round 15
// speedup vs baseline: 1.1718x; 1.1718x over previous
#include <cuda_runtime.h>
#include <cuda_fp16.h>
#include <cstdint>
#include <cstddef>

// ---------------- problem constants ----------------
#define DD     1024
#define PCOLS  405       // 1 + 80 + 324
#define NTILE  4
#define BNL    104       // live cols per tile
#define BNP    112       // padded rows per tile
#define NF     300
#define NMAX   65536
#define BM     128
#define BK     64        // fp16: 64 halves = 128B rows -> SW128 swizzle
#define NCHUNK (DD / BK) // 16
#define NSTAGE 3

#define A_BYTES  (BM * 128)              // 16384
#define B_BYTES  (BNP * 128)             // 14336
#define STAGE_SZ (A_BYTES + B_BYTES)     // 30720
#define SMEM_DYN (1024 + NSTAGE * STAGE_SZ)  // 93184 -> 2 CTAs/SM
#define LDC      120

// ---------------- device scratch ----------------
__device__ __half g_xh[(size_t)NMAX * DD];        // 128 MB fp16 x
__device__ __half g_Wh[(size_t)NTILE * BNP * DD];
__device__ float  g_bias[NTILE * BNP];

// ---------------- helpers ----------------
__device__ __forceinline__ uint32_t smem_u32(const void* p) {
    uint32_t a;
    asm("{ .reg .u64 t; cvta.to.shared.u64 t, %1; cvt.u32.u64 %0, t; }" : "=r"(a) : "l"(p));
    return a;
}
__device__ __forceinline__ void cpa16(uint32_t dst, const void* src) {
    asm volatile("cp.async.cg.shared.global [%0], [%1], 16;" :: "r"(dst), "l"(src));
}
__device__ __forceinline__ void ldsm4(uint32_t r[4], uint32_t addr) {
    asm volatile("ldmatrix.sync.aligned.m8n8.x4.shared.b16 {%0,%1,%2,%3}, [%4];"
        : "=r"(r[0]), "=r"(r[1]), "=r"(r[2]), "=r"(r[3]) : "r"(addr));
}
__device__ __forceinline__ void mma16(float d[4], const uint32_t a[4], uint32_t b0, uint32_t b1) {
    asm volatile(
        "mma.sync.aligned.m16n8k16.row.col.f32.f16.f16.f32 "
        "{%0,%1,%2,%3}, {%4,%5,%6,%7}, {%8,%9}, {%0,%1,%2,%3};"
        : "+f"(d[0]), "+f"(d[1]), "+f"(d[2]), "+f"(d[3])
        : "r"(a[0]), "r"(a[1]), "r"(a[2]), "r"(a[3]), "r"(b0), "r"(b1));
}
__device__ __forceinline__ uint4 pack8(float4 a, float4 b) {
    __half2 h0 = __floats2half2_rn(a.x, a.y);
    __half2 h1 = __floats2half2_rn(a.z, a.w);
    __half2 h2 = __floats2half2_rn(b.x, b.y);
    __half2 h3 = __floats2half2_rn(b.z, b.w);
    uint4 u;
    u.x = *reinterpret_cast<uint32_t*>(&h0);
    u.y = *reinterpret_cast<uint32_t*>(&h1);
    u.z = *reinterpret_cast<uint32_t*>(&h2);
    u.w = *reinterpret_cast<uint32_t*>(&h3);
    return u;
}

// ---------------- k_cvt: x fp32 -> fp16, streaming (R12 exact, 57us measured) ----
__global__ void k_cvt(const float4* __restrict__ xi, int n8) {
    uint4* xo = reinterpret_cast<uint4*>(g_xh);
    int i = blockIdx.x * blockDim.x + threadIdx.x;
    if (i < n8) {
        float4 a = xi[2 * i], b = xi[2 * i + 1];
        xo[i] = pack8(a, b);
    }
}

// ---------------- k_fold: R12 exact — grid (8 cols x 20 rows), 128 thr ----------
__global__ void k_fold(const float* __restrict__ Wsem, const float* __restrict__ bsem,
                       const float* __restrict__ semm) {
    __shared__ float ssm[4 * NF];
    __shared__ float sscale[4];
    const int cg = blockIdx.x;        // 0..7 (128 cols)
    const int rg = blockIdx.y;        // 0..19 (4 rows)
    const int t = threadIdx.x, wid = t >> 5, lane = t & 31;
    const int r0 = rg * 4, c0 = cg * 128;

    {   // warp w -> norm of row w
        const float* src = semm + (size_t)(r0 + wid) * NF;
        float ss = 0.f;
        for (int f = lane; f < NF; f += 32) { float v = src[f]; ss += v * v; }
        for (int o = 16; o; o >>= 1) ss += __shfl_xor_sync(~0u, ss, o);
        if (lane == 0) sscale[wid] = 8.0f * rsqrtf(ss);
    }
    __syncthreads();
    for (int idx = t; idx < 4 * NF; idx += 128) {
        int ri = idx / NF, f = idx - ri * NF;
        ssm[ri * NF + f] = semm[(size_t)(r0 + ri) * NF + f] * sscale[ri];
    }
    __syncthreads();

    float acc[4] = {0.f, 0.f, 0.f, 0.f};
    const float* wp = Wsem + c0 + t;
#pragma unroll 10
    for (int f = 0; f < NF; f++) {
        float w = wp[(size_t)f * DD];
#pragma unroll
        for (int ri = 0; ri < 4; ri++) acc[ri] += ssm[ri * NF + f] * w;
    }
#pragma unroll
    for (int ri = 0; ri < 4; ri++)
        g_Wh[(size_t)(1 + r0 + ri) * DD + c0 + t] = __float2half_rn(acc[ri]);

    if (cg == 0) {   // warp w -> bias of row w
        float bb = 0.f;
        for (int f = lane; f < NF; f += 32) bb += ssm[wid * NF + f] * bsem[f];
        for (int o = 16; o; o >>= 1) bb += __shfl_xor_sync(~0u, bb, o);
        if (lane == 0) g_bias[1 + r0 + wid] = bb;
    }
}

// ---------------- k_copy: R12 exact ----------------
__global__ void k_copy(const float* __restrict__ Wcls, const float* __restrict__ bcls,
                       const float* __restrict__ Wbb,  const float* __restrict__ bbb) {
    const int p = blockIdx.x, t = threadIdx.x;
    const int tile = p / BNP, r = p - tile * BNP;
    const int j = tile * BNL + r;
    __half* wo = g_Wh + (size_t)p * DD;
    if (r >= BNL || j >= PCOLS) {
        for (int d = t; d < DD; d += 256) wo[d] = __float2half_rn(0.f);
        if (t == 0) g_bias[p] = 0.f;
    } else if (j == 0) {
        for (int d = t; d < DD; d += 256) wo[d] = __float2half_rn(Wcls[d]);
        if (t == 0) g_bias[p] = bcls[0];
    } else if (j <= 80) {
        // written by k_fold
    } else {
        const int i = j - 81;
        for (int d = t; d < DD; d += 256) wo[d] = __float2half_rn(Wbb[(size_t)i * DD + d]);
        if (t == 0) g_bias[p] = bbb[i];
    }
}

// ---------------- main GEMM: R13 exact (182.0us measured) ----------------
__device__ __forceinline__ void issueA(uint32_t sbase, const __half* __restrict__ xs, int tid) {
#pragma unroll
    for (int i = 0; i < 4; i++) {               // A: 128 rows x 8 quads = 1024
        int seg = tid + i * 256;
        int row = seg >> 3, q = seg & 7;
        cpa16(sbase + (uint32_t)(row * 128 + ((q ^ (row & 7)) << 4)),
              xs + (size_t)row * DD + q * 8);
    }
}
__device__ __forceinline__ void issueB(uint32_t sbase, const __half* __restrict__ ws, int tid) {
#pragma unroll
    for (int i = 0; i < 4; i++) {               // B: 112 rows x 8 quads = 896
        int seg = tid + i * 256;
        if (seg < BNP * 8) {
            int row = seg >> 3, q = seg & 7;
            cpa16(sbase + (uint32_t)(A_BYTES + row * 128 + ((q ^ (row & 7)) << 4)),
                  ws + (size_t)row * DD + q * 8);
        }
    }
    asm volatile("cp.async.commit_group;" ::: "memory");
}

template <int NJ0, int NJ1, int NB1, int LIVE>
__device__ __forceinline__ void gemm_body(char* sm, float* __restrict__ out, int N, int nt) {
    const int tid = threadIdx.x, wid = tid >> 5, lane = tid & 31;
    const int warp_m = wid & 3;
    const int warp_n = wid >> 2;
    const size_t row0 = (size_t)blockIdx.y * BM;
    const size_t NS = (size_t)N * 81;
    const int NJ = warp_n ? NJ1 : NJ0;
    const int colbase = warp_n ? NB1 : 0;

    float* sBias = (float*)sm;
    for (int i = tid; i < BNP; i += 256) sBias[i] = g_bias[nt * BNP + i];

    uint32_t st[NSTAGE];
#pragma unroll
    for (int s = 0; s < NSTAGE; s++) st[s] = smem_u32(sm + 1024 + s * STAGE_SZ);

    const __half* xrow0 = g_xh + row0 * DD;
    const __half* wrow0 = g_Wh + (size_t)nt * BNP * DD;

    const int rAr = warp_m * 32 + ((lane >> 3) & 1) * 8 + (lane & 7);
    const int qbA = lane >> 4;
    const uint32_t abase0 = (uint32_t)rAr * 128, abase1 = (uint32_t)(rAr + 16) * 128;
    const uint32_t axor = (uint32_t)(rAr & 7);
    const int rBr = colbase + (lane >> 4) * 8 + (lane & 7);
    const int qbB = (lane >> 3) & 1;
    uint32_t bbase[4];
#pragma unroll
    for (int g = 0; g < 4; g++) bbase[g] = (uint32_t)(rBr + g * 16) * 128;
    const uint32_t bxor = (uint32_t)(rBr & 7);

    float acc[2][NJ0][4];
#pragma unroll
    for (int mi = 0; mi < 2; mi++)
#pragma unroll
        for (int nj = 0; nj < NJ0; nj++)
#pragma unroll
            for (int e = 0; e < 4; e++) acc[mi][nj][e] = 0.f;

    issueA(st[0], xrow0, tid);           issueB(st[0], wrow0, tid);
    issueA(st[1], xrow0 + BK, tid);      issueB(st[1], wrow0 + BK, tid);

    for (int c = 0; c < NCHUNK; c++) {
        uint32_t Ab = st[c % NSTAGE], Bb = Ab + A_BYTES;
        if (c == NCHUNK - 1) asm volatile("cp.async.wait_group 0;" ::: "memory");
        else                 asm volatile("cp.async.wait_group 1;" ::: "memory");
        __syncthreads();
        const bool pre = (c + 2 < NCHUNK);
        const uint32_t stn = st[(c + 2) % NSTAGE];

#pragma unroll
        for (int kq = 0; kq < 4; kq++) {
            uint32_t a0[4], a1[4];
            uint32_t qsel = (uint32_t)((2 * kq + qbA) ^ axor) << 4;
            ldsm4(a0, Ab + abase0 + qsel);
            ldsm4(a1, Ab + abase1 + qsel);
            uint32_t qselB = (uint32_t)((2 * kq + qbB) ^ bxor) << 4;
            if (warp_n == 0) {
#pragma unroll
                for (int g = 0; g < 4; g++) {
                    if (g < (NJ0 + 1) / 2) {
                        uint32_t b[4];
                        ldsm4(b, Bb + bbase[g] + qselB);
                        if (2 * g < NJ0)     { mma16(acc[0][2 * g],     a0, b[0], b[1]);
                                               mma16(acc[1][2 * g],     a1, b[0], b[1]); }
                        if (2 * g + 1 < NJ0) { mma16(acc[0][2 * g + 1], a0, b[2], b[3]);
                                               mma16(acc[1][2 * g + 1], a1, b[2], b[3]); }
                    }
                }
            } else {
#pragma unroll
                for (int g = 0; g < 4; g++) {
                    if (g < (NJ1 + 1) / 2) {
                        uint32_t b[4];
                        ldsm4(b, Bb + bbase[g] + qselB);
                        if (2 * g < NJ1)     { mma16(acc[0][2 * g],     a0, b[0], b[1]);
                                               mma16(acc[1][2 * g],     a1, b[0], b[1]); }
                        if (2 * g + 1 < NJ1) { mma16(acc[0][2 * g + 1], a0, b[2], b[3]);
                                               mma16(acc[1][2 * g + 1], a1, b[2], b[3]); }
                    }
                }
            }
            // spread the refill: A-half after kq0, B-half (+commit) after kq1
            if (kq == 0 && pre) issueA(stn, xrow0 + (size_t)(c + 2) * BK, tid);
            if (kq == 1 && pre) issueB(stn, wrow0 + (size_t)(c + 2) * BK, tid);
        }
    }
    __syncthreads();

    // ---- epilogue ----
    float* sC = (float*)(sm + 1024);
    const int tr = lane >> 2, tc2 = (lane & 3) * 2;
#pragma unroll
    for (int mi = 0; mi < 2; mi++)
#pragma unroll
        for (int nj = 0; nj < NJ0; nj++)
            if (nj < NJ) {
                int r = warp_m * 32 + mi * 16 + tr;
                int cc = colbase + nj * 8 + tc2;
                *(float2*)&sC[r * LDC + cc]       = make_float2(acc[mi][nj][0], acc[mi][nj][1]);
                *(float2*)&sC[(r + 8) * LDC + cc] = make_float2(acc[mi][nj][2], acc[mi][nj][3]);
            }
    __syncthreads();

    float* outb = out + NS;
    const int jbase = nt * BNL;
    for (int e = tid; e < BM * LIVE; e += 256) {
        int row = e / LIVE, n = e - row * LIVE;
        int j = jbase + n;
        float v = sC[row * LDC + n] + sBias[n];
        size_t gr = row0 + row;
        if (j < 81) __stcs(&out[gr * 81 + j], v);
        else        __stcs(&outb[gr * 324 + (j - 81)], v);
    }
}

__global__ __launch_bounds__(256, 2) void k_main(float* __restrict__ out, int N) {
    extern __shared__ char sm[];
    const int nt = blockIdx.x;
    if (nt < 3) gemm_body<7, 6, 56, 104>(sm, out, N, nt);
    else        gemm_body<6, 6, 48, 93>(sm, out, N, nt);
}

// ---------------- launch ----------------
extern "C" void kernel_launch(void* const* d_in, const int* in_sizes, int n_in,
                              void* d_out, int out_size) {
    const float* x    = (const float*)d_in[0];
    const float* Wcls = (const float*)d_in[1];
    const float* bcls = (const float*)d_in[2];
    const float* Wsem = (const float*)d_in[3];
    const float* bsem = (const float*)d_in[4];
    const float* Wbb  = (const float*)d_in[5];
    const float* bbb  = (const float*)d_in[6];
    const float* semm = (const float*)d_in[7];
    float* out = (float*)d_out;
    int N = in_sizes[0] / DD;

    cudaFuncSetAttribute(k_main, cudaFuncAttributeMaxDynamicSharedMemorySize, SMEM_DYN);

    int n8 = N * DD / 8;
    k_cvt<<<(n8 + 255) / 256, 256>>>((const float4*)x, n8);
    k_fold<<<dim3(8, 20), 128>>>(Wsem, bsem, semm);
    k_copy<<<NTILE * BNP, 256>>>(Wcls, bcls, Wbb, bbb);
    dim3 grid(NTILE, N / BM);
    k_main<<<grid, 256, SMEM_DYN>>>(out, N);
}